// round 8
// baseline (speedup 1.0000x reference)
#include <cuda_runtime.h>
#include <cuda_bf16.h>
#include <cstdint>

#define HGRID 768
#define WGRID 768
#define NMAX  200064   // 1563 * 128

// Scratch in __device__ globals (no allocation allowed).
__device__ int g_idx_map[HGRID * WGRID];
// h1 as interleaved bf16 split planes: per row {128B hi, 128B lo}
__device__ __align__(16) unsigned char g_h1b[(size_t)NMAX * 256];
// B fragments (uint4 = {bhi0,bhi1,blo0,blo1}):
__device__ uint4 g_w2f[9 * 4 * 8 * 32];   // w2: [tap][kc(4)][nt(8)][lane(32)]
__device__ uint4 g_w3f[4 * 4 * 8 * 32];   // w3: [cb(4)][kc(4)][nt(8)][lane(32)]

// ---------------------------------------------------------------------------
__device__ __forceinline__ int coords_is64(const int* c) { return c[1] == 0; }
__device__ __forceinline__ int load_coord(const int* c, int is64, int i) {
    return is64 ? c[2 * i] : c[i];
}
__device__ __forceinline__ void bsplit2(float a, float b, uint32_t& hi, uint32_t& lo) {
    __nv_bfloat16 ah = __float2bfloat16(a);
    __nv_bfloat16 bh = __float2bfloat16(b);
    float ar = a - __bfloat162float(ah);
    float br = b - __bfloat162float(bh);
    __nv_bfloat162 h; h.x = ah; h.y = bh;
    __nv_bfloat162 l; l.x = __float2bfloat16(ar); l.y = __float2bfloat16(br);
    hi = *reinterpret_cast<uint32_t*>(&h);
    lo = *reinterpret_cast<uint32_t*>(&l);
}
__device__ __forceinline__ uint32_t smem_u32(const void* p) {
    uint32_t a;
    asm("{ .reg .u64 t; cvta.to.shared.u64 t, %1; cvt.u32.u64 %0, t; }"
        : "=r"(a) : "l"(p));
    return a;
}
__device__ __forceinline__ void cp_async16(uint32_t dst, const void* src, int srcsize) {
    asm volatile("cp.async.ca.shared.global [%0], [%1], 16, %2;"
                 :: "r"(dst), "l"(src), "r"(srcsize) : "memory");
}
#define CP_COMMIT() asm volatile("cp.async.commit_group;" ::: "memory")
#define CP_WAIT0()  asm volatile("cp.async.wait_group 0;" ::: "memory")

// mma.sync m16n8k16 bf16 -> f32 accumulate
__device__ __forceinline__ void mma16816(float c[4], const uint32_t a[4],
                                         uint32_t b0, uint32_t b1) {
    asm volatile(
        "mma.sync.aligned.m16n8k16.row.col.f32.bf16.bf16.f32 "
        "{%0,%1,%2,%3}, {%4,%5,%6,%7}, {%8,%9}, {%0,%1,%2,%3};"
        : "+f"(c[0]), "+f"(c[1]), "+f"(c[2]), "+f"(c[3])
        : "r"(a[0]), "r"(a[1]), "r"(a[2]), "r"(a[3]), "r"(b0), "r"(b1));
}

// ---------------------------------------------------------------------------
// util1: clear idx_map (all threads) + prep w2 B-fragments (first 9216)
__global__ void util1_kernel(const float* __restrict__ w2) {
    int i = blockIdx.x * blockDim.x + threadIdx.x;
    if (i < HGRID * WGRID) g_idx_map[i] = -1;
    if (i < 9 * 4 * 8 * 32) {
        int lane = i & 31, nt = (i >> 5) & 7, kc = (i >> 8) & 3, tap = i >> 10;
        int n  = nt * 8 + (lane >> 2);
        int k0 = kc * 16 + (lane & 3) * 2;
        uint32_t hi[2], lo[2];
#pragma unroll
        for (int j = 0; j < 2; ++j) {
            int k = k0 + j * 8;
            bsplit2(w2[tap * 4096 + k * 64 + n], w2[tap * 4096 + (k + 1) * 64 + n],
                    hi[j], lo[j]);
        }
        g_w2f[i] = make_uint4(hi[0], hi[1], lo[0], lo[1]);
    }
}

// util2: scatter coords -> idx_map + prep w3 B-fragments (first 4096)
__global__ void util2_kernel(const int* __restrict__ coords,
                             const float* __restrict__ w3, int n) {
    int i = blockIdx.x * blockDim.x + threadIdx.x;
    if (i < n) {
        int is64 = coords_is64(coords);
        g_idx_map[load_coord(coords, is64, i)] = i;
    }
    if (i < 4 * 4 * 8 * 32) {
        int lane = i & 31, nt = (i >> 5) & 7, kc = (i >> 8) & 3, cb = i >> 10;
        int nn = cb * 64 + nt * 8 + (lane >> 2);
        int k0 = kc * 16 + (lane & 3) * 2;
        uint32_t hi[2], lo[2];
#pragma unroll
        for (int j = 0; j < 2; ++j) {
            int k = k0 + j * 8;
            bsplit2(w3[k * 256 + nn], w3[(k + 1) * 256 + nn], hi[j], lo[j]);
        }
        g_w3f[i] = make_uint4(hi[0], hi[1], lo[0], lo[1]);
    }
}

// ---------------------------------------------------------------------------
// FFMA micro-kernel (conv1)
template <int LDA>
__device__ __forceinline__ void mm32(const float* __restrict__ sA,
                                     const float* __restrict__ sB,
                                     int trow, int tcol, float acc[8][4]) {
#pragma unroll
    for (int k = 0; k < 32; ++k) {
        float4 b = *(const float4*)(sB + k * 64 + tcol);
#pragma unroll
        for (int i = 0; i < 8; ++i) {
            float a = sA[(trow + i) * LDA + k];
            acc[i][0] = fmaf(a, b.x, acc[i][0]);
            acc[i][1] = fmaf(a, b.y, acc[i][1]);
            acc[i][2] = fmaf(a, b.z, acc[i][2]);
            acc[i][3] = fmaf(a, b.w, acc[i][3]);
        }
    }
}

// conv1: h1 = relu((feats @ w1) * s1 + b1) -> bf16 hi/lo planes  (R5 version)
__global__ void __launch_bounds__(256) conv1_kernel(
    const float* __restrict__ feats, const float* __restrict__ w1,
    const float* __restrict__ s1, const float* __restrict__ b1, int n)
{
    __shared__ __align__(16) float sA[128 * 33];
    __shared__ __align__(16) float sB[32 * 64];
    const int tid = threadIdx.x;
    const int site0 = blockIdx.x * 128;
    const int trow = (tid >> 4) << 3;
    const int tcol = (tid & 15) << 2;

    float acc[8][4];
#pragma unroll
    for (int i = 0; i < 8; ++i)
#pragma unroll
        for (int j = 0; j < 4; ++j) acc[i][j] = 0.f;

#pragma unroll 1
    for (int k0 = 0; k0 < 256; k0 += 32) {
#pragma unroll
        for (int l = 0; l < 4; ++l) {
            int i = tid + l * 256;
            int r = i >> 3, c4 = (i & 7) << 2;
            int site = site0 + r;
            float4 v = make_float4(0.f, 0.f, 0.f, 0.f);
            if (site < n) v = *(const float4*)&feats[(size_t)site * 256 + k0 + c4];
            sA[r * 33 + c4 + 0] = v.x; sA[r * 33 + c4 + 1] = v.y;
            sA[r * 33 + c4 + 2] = v.z; sA[r * 33 + c4 + 3] = v.w;
        }
#pragma unroll
        for (int l = 0; l < 2; ++l) {
            int i = tid + l * 256;
            int r = i >> 4, c4 = (i & 15) << 2;
            *(float4*)&sB[r * 64 + c4] = *(const float4*)&w1[(size_t)(k0 + r) * 64 + c4];
        }
        __syncthreads();
        mm32<33>(sA, sB, trow, tcol, acc);
        __syncthreads();
    }

    float sc[4], bi[4];
#pragma unroll
    for (int j = 0; j < 4; ++j) { sc[j] = s1[tcol + j]; bi[j] = b1[tcol + j]; }
#pragma unroll
    for (int i = 0; i < 8; ++i) {
        int site = site0 + trow + i;   // < NMAX always; OOB rows never read back
        float v0 = fmaxf(fmaf(acc[i][0], sc[0], bi[0]), 0.f);
        float v1 = fmaxf(fmaf(acc[i][1], sc[1], bi[1]), 0.f);
        float v2 = fmaxf(fmaf(acc[i][2], sc[2], bi[2]), 0.f);
        float v3 = fmaxf(fmaf(acc[i][3], sc[3], bi[3]), 0.f);
        uint32_t h0, l0, h1v, l1v;
        bsplit2(v0, v1, h0, l0);
        bsplit2(v2, v3, h1v, l1v);
        unsigned char* row = g_h1b + (size_t)site * 256;
        *(uint2*)(row + tcol * 2)       = make_uint2(h0, h1v);   // hi plane
        *(uint2*)(row + 128 + tcol * 2) = make_uint2(l0, l1v);   // lo plane
    }
}

// ---------------------------------------------------------------------------
// FUSED conv2 + conv3 (block-phased, cp.async double-buffered gathers):
//   h2 = relu(sparse3x3(h1) * s2 + b2)   (registers only, never stored)
//   out = relu((h2 @ w3) * s3 + b3 + feats)
#define LDP 144                        // bytes per row per plane
#define PLANE (128 * LDP)              // 18432
#define ABUF  (2 * PLANE)              // 36864 per buffer
// dynamic smem layout (bytes):
#define SM_SC    0                     // 640 floats = 2560
#define SM_NBR   2560                  // 9*128*4 = 4608
#define SM_BUF   7680                  // 2 * ABUF (128-aligned)
#define SM_TOTAL (SM_BUF + 2 * ABUF)   // 81408

__global__ void __launch_bounds__(256) conv23_kernel(
    const int* __restrict__ coords,
    const float* __restrict__ s2, const float* __restrict__ b2,
    const float* __restrict__ feats,
    const float* __restrict__ s3, const float* __restrict__ b3,
    float* __restrict__ out, int n)
{
    extern __shared__ __align__(128) char dsm[];
    float* s_s2 = (float*)(dsm + SM_SC);
    float* s_b2 = s_s2 + 64;
    float* s_s3 = s_b2 + 64;
    float* s_b3 = s_s3 + 256;
    int*  s_nbr = (int*)(dsm + SM_NBR);
    unsigned char* bufs = (unsigned char*)(dsm + SM_BUF);

    const int tid = threadIdx.x, wid = tid >> 5, lane = tid & 31;
    const int site0 = blockIdx.x * 128;
    const int rw = wid * 16;
    const int r2 = tid >> 1, half = tid & 1;   // loader: row, plane

    if (tid < 64) { s_s2[tid] = s2[tid]; s_b2[tid] = b2[tid]; }
    s_s3[tid] = s3[tid]; s_b3[tid] = b3[tid];
    if (tid < 128) {
#pragma unroll
        for (int t = 0; t < 9; ++t) s_nbr[t * 128 + tid] = -1;
        int site = site0 + tid;
        if (site < n) {
            int is64 = coords_is64(coords);
            int c = load_coord(coords, is64, site);
            int y = c / WGRID, x = c % WGRID;
#pragma unroll
            for (int t = 0; t < 9; ++t) {
                int ny = y + t / 3 - 1, nx = x + t % 3 - 1;
                if (ny >= 0 && ny < HGRID && nx >= 0 && nx < WGRID)
                    s_nbr[t * 128 + tid] = g_idx_map[ny * WGRID + nx];
            }
        }
    }
    __syncthreads();

    float acc[8][4];
#pragma unroll
    for (int t = 0; t < 8; ++t)
#pragma unroll
        for (int j = 0; j < 4; ++j) acc[t][j] = 0.f;

    const uint32_t mydst = smem_u32(bufs) + half * PLANE + r2 * LDP;

    // prologue: tap 0 -> buf 0
    {
        int nb = s_nbr[r2];
        const unsigned char* src =
            g_h1b + (size_t)(nb < 0 ? 0 : nb) * 256 + half * 128;
        int ok = (nb >= 0) ? 16 : 0;
#pragma unroll
        for (int j = 0; j < 8; ++j) cp_async16(mydst + j * 16, src + j * 16, ok);
        CP_COMMIT();
    }

    // ---------------- conv2: 9-tap sparse 3x3 accumulation ----------------
#pragma unroll 1
    for (int tap = 0; tap < 9; ++tap) {
        CP_WAIT0();
        __syncthreads();                     // buf(tap&1) ready; prev readers done
        if (tap < 8) {                       // prefetch tap+1 into other buffer
            int nb = s_nbr[(tap + 1) * 128 + r2];
            const unsigned char* src =
                g_h1b + (size_t)(nb < 0 ? 0 : nb) * 256 + half * 128;
            int ok = (nb >= 0) ? 16 : 0;
            uint32_t dst = mydst + ((tap + 1) & 1) * ABUF;
#pragma unroll
            for (int j = 0; j < 8; ++j) cp_async16(dst + j * 16, src + j * 16, ok);
            CP_COMMIT();
        }

        const unsigned char* wbase = bufs + (tap & 1) * ABUF;
        const uint4* wf = g_w2f + (size_t)tap * 1024 + lane;
#pragma unroll
        for (int kc = 0; kc < 4; ++kc) {
            uint32_t ab = (uint32_t)((rw + (lane >> 2)) * LDP + kc * 32 + (lane & 3) * 4);
            uint32_t ah[4], al[4];
            ah[0] = *(const uint32_t*)(wbase + ab);
            ah[1] = *(const uint32_t*)(wbase + ab + 8 * LDP);
            ah[2] = *(const uint32_t*)(wbase + ab + 16);
            ah[3] = *(const uint32_t*)(wbase + ab + 8 * LDP + 16);
            al[0] = *(const uint32_t*)(wbase + PLANE + ab);
            al[1] = *(const uint32_t*)(wbase + PLANE + ab + 8 * LDP);
            al[2] = *(const uint32_t*)(wbase + PLANE + ab + 16);
            al[3] = *(const uint32_t*)(wbase + PLANE + ab + 8 * LDP + 16);
#pragma unroll
            for (int nt = 0; nt < 8; ++nt) {
                uint4 b = wf[kc * 256 + nt * 32];
                mma16816(acc[nt], ah, b.x, b.y);
                mma16816(acc[nt], ah, b.z, b.w);
                mma16816(acc[nt], al, b.x, b.y);
            }
        }
    }

    // ------- bn2 + relu in registers; repackage C-frags as A-frags --------
    uint32_t fh[4][4], fl[4][4];
    {
        const int n0 = (lane & 3) * 2;
#pragma unroll
        for (int kc = 0; kc < 4; ++kc) {
#pragma unroll
            for (int q = 0; q < 2; ++q) {
                int nt = 2 * kc + q;
                int c0 = nt * 8 + n0;
                float v0 = fmaxf(fmaf(acc[nt][0], s_s2[c0],     s_b2[c0]),     0.f);
                float v1 = fmaxf(fmaf(acc[nt][1], s_s2[c0 + 1], s_b2[c0 + 1]), 0.f);
                float v2 = fmaxf(fmaf(acc[nt][2], s_s2[c0],     s_b2[c0]),     0.f);
                float v3 = fmaxf(fmaf(acc[nt][3], s_s2[c0 + 1], s_b2[c0 + 1]), 0.f);
                bsplit2(v0, v1, fh[kc][2 * q],     fl[kc][2 * q]);
                bsplit2(v2, v3, fh[kc][2 * q + 1], fl[kc][2 * q + 1]);
            }
        }
    }

    // ---------------- conv3: 4 column blocks of 64, from registers --------
    float* stg = (float*)bufs;   // 128 x 64 f32 staging = 32KB (fits buffer 0)
#pragma unroll 1
    for (int cb = 0; cb < 4; ++cb) {
        float acc2[8][4];
#pragma unroll
        for (int t = 0; t < 8; ++t)
#pragma unroll
            for (int j = 0; j < 4; ++j) acc2[t][j] = 0.f;

        const uint4* wf = g_w3f + (size_t)cb * 1024 + lane;
#pragma unroll
        for (int kc = 0; kc < 4; ++kc) {
#pragma unroll
            for (int nt = 0; nt < 8; ++nt) {
                uint4 b = wf[kc * 256 + nt * 32];
                mma16816(acc2[nt], fh[kc], b.x, b.y);
                mma16816(acc2[nt], fh[kc], b.z, b.w);
                mma16816(acc2[nt], fl[kc], b.x, b.y);
            }
        }
        __syncthreads();   // prior stg readers (or tap-8 readers at cb=0) done
        {
            int r0 = rw + (lane >> 2);
            int n0 = (lane & 3) * 2;
#pragma unroll
            for (int nt = 0; nt < 8; ++nt) {
                int c  = nt * 8 + n0;
                int cg = cb * 64 + c;
                stg[r0 * 64 + c]           = fmaf(acc2[nt][0], s_s3[cg],     s_b3[cg]);
                stg[r0 * 64 + c + 1]       = fmaf(acc2[nt][1], s_s3[cg + 1], s_b3[cg + 1]);
                stg[(r0 + 8) * 64 + c]     = fmaf(acc2[nt][2], s_s3[cg],     s_b3[cg]);
                stg[(r0 + 8) * 64 + c + 1] = fmaf(acc2[nt][3], s_s3[cg + 1], s_b3[cg + 1]);
            }
        }
        __syncthreads();
        {
            int site = site0 + r2;
            if (site < n) {
                const float4* idn =
                    (const float4*)&feats[(size_t)site * 256 + cb * 64 + half * 32];
                const float4* s = (const float4*)(stg + r2 * 64 + half * 32);
                float4* dst = (float4*)&out[(size_t)site * 256 + cb * 64 + half * 32];
#pragma unroll
                for (int j = 0; j < 8; ++j) {
                    float4 a = s[j], b = idn[j], o;
                    o.x = fmaxf(a.x + b.x, 0.f);
                    o.y = fmaxf(a.y + b.y, 0.f);
                    o.z = fmaxf(a.z + b.z, 0.f);
                    o.w = fmaxf(a.w + b.w, 0.f);
                    dst[j] = o;
                }
            }
        }
    }
}

// ---------------------------------------------------------------------------
extern "C" void kernel_launch(void* const* d_in, const int* in_sizes, int n_in,
                              void* d_out, int out_size) {
    const float* feats  = (const float*)d_in[0];
    const int*   coords = (const int*)d_in[1];
    const float* w1     = (const float*)d_in[2];
    const float* w2     = (const float*)d_in[3];
    const float* w3     = (const float*)d_in[4];
    const float* s1     = (const float*)d_in[5];
    const float* b1     = (const float*)d_in[6];
    const float* s2     = (const float*)d_in[7];
    const float* b2     = (const float*)d_in[8];
    const float* s3     = (const float*)d_in[9];
    const float* b3     = (const float*)d_in[10];
    float* out = (float*)d_out;

    const int n = in_sizes[0] / 256;
    const int tiles = (n + 127) / 128;

    cudaFuncSetAttribute(conv23_kernel,
                         cudaFuncAttributeMaxDynamicSharedMemorySize, SM_TOTAL);

    // 4 launches; conv23 is launch #4 so ncu (-s/-c window) captures it.
    util1_kernel<<<(HGRID * WGRID + 255) / 256, 256>>>(w2);                 // #1
    util2_kernel<<<(max(n, 4096) + 255) / 256, 256>>>(coords, w3, n);       // #2
    conv1_kernel<<<tiles, 256>>>(feats, w1, s1, b1, n);                     // #3
    conv23_kernel<<<tiles, 256, SM_TOTAL>>>(coords, s2, b2, feats, s3, b3, out, n);  // #4
}

// round 9
// speedup vs baseline: 1.1309x; 1.1309x over previous
#include <cuda_runtime.h>
#include <cuda_bf16.h>
#include <cstdint>

#define HGRID 768
#define WGRID 768
#define NMAX  200064   // 1563 * 128

// Scratch in __device__ globals (no allocation allowed).
__device__ int g_idx_map[HGRID * WGRID];
// h1 as interleaved bf16 split planes: per row {128B hi, 128B lo}
__device__ __align__(16) unsigned char g_h1b[(size_t)NMAX * 256];
// B fragments (uint4 = {bhi0,bhi1,blo0,blo1}):
__device__ uint4 g_w2f[9 * 4 * 8 * 32];   // w2: [tap][kc(4)][nt(8)][lane(32)]
__device__ uint4 g_w3f[4 * 4 * 8 * 32];   // w3: [cb(4)][kc(4)][nt(8)][lane(32)]

// ---------------------------------------------------------------------------
__device__ __forceinline__ int coords_is64(const int* c) { return c[1] == 0; }
__device__ __forceinline__ int load_coord(const int* c, int is64, int i) {
    return is64 ? c[2 * i] : c[i];
}
__device__ __forceinline__ void bsplit2(float a, float b, uint32_t& hi, uint32_t& lo) {
    __nv_bfloat16 ah = __float2bfloat16(a);
    __nv_bfloat16 bh = __float2bfloat16(b);
    float ar = a - __bfloat162float(ah);
    float br = b - __bfloat162float(bh);
    __nv_bfloat162 h; h.x = ah; h.y = bh;
    __nv_bfloat162 l; l.x = __float2bfloat16(ar); l.y = __float2bfloat16(br);
    hi = *reinterpret_cast<uint32_t*>(&h);
    lo = *reinterpret_cast<uint32_t*>(&l);
}

// mma.sync m16n8k16 bf16 -> f32 accumulate
__device__ __forceinline__ void mma16816(float c[4], const uint32_t a[4],
                                         uint32_t b0, uint32_t b1) {
    asm volatile(
        "mma.sync.aligned.m16n8k16.row.col.f32.bf16.bf16.f32 "
        "{%0,%1,%2,%3}, {%4,%5,%6,%7}, {%8,%9}, {%0,%1,%2,%3};"
        : "+f"(c[0]), "+f"(c[1]), "+f"(c[2]), "+f"(c[3])
        : "r"(a[0]), "r"(a[1]), "r"(a[2]), "r"(a[3]), "r"(b0), "r"(b1));
}

// ---------------------------------------------------------------------------
// util1: clear idx_map (all threads) + prep w2 B-fragments (first 9216)
__global__ void util1_kernel(const float* __restrict__ w2) {
    int i = blockIdx.x * blockDim.x + threadIdx.x;
    if (i < HGRID * WGRID) g_idx_map[i] = -1;
    if (i < 9 * 4 * 8 * 32) {
        int lane = i & 31, nt = (i >> 5) & 7, kc = (i >> 8) & 3, tap = i >> 10;
        int n  = nt * 8 + (lane >> 2);
        int k0 = kc * 16 + (lane & 3) * 2;
        uint32_t hi[2], lo[2];
#pragma unroll
        for (int j = 0; j < 2; ++j) {
            int k = k0 + j * 8;
            bsplit2(w2[tap * 4096 + k * 64 + n], w2[tap * 4096 + (k + 1) * 64 + n],
                    hi[j], lo[j]);
        }
        g_w2f[i] = make_uint4(hi[0], hi[1], lo[0], lo[1]);
    }
}

// util2: scatter coords -> idx_map + prep w3 B-fragments (first 4096)
__global__ void util2_kernel(const int* __restrict__ coords,
                             const float* __restrict__ w3, int n) {
    int i = blockIdx.x * blockDim.x + threadIdx.x;
    if (i < n) {
        int is64 = coords_is64(coords);
        g_idx_map[load_coord(coords, is64, i)] = i;
    }
    if (i < 4 * 4 * 8 * 32) {
        int lane = i & 31, nt = (i >> 5) & 7, kc = (i >> 8) & 3, cb = i >> 10;
        int nn = cb * 64 + nt * 8 + (lane >> 2);
        int k0 = kc * 16 + (lane & 3) * 2;
        uint32_t hi[2], lo[2];
#pragma unroll
        for (int j = 0; j < 2; ++j) {
            int k = k0 + j * 8;
            bsplit2(w3[k * 256 + nn], w3[(k + 1) * 256 + nn], hi[j], lo[j]);
        }
        g_w3f[i] = make_uint4(hi[0], hi[1], lo[0], lo[1]);
    }
}

// ---------------------------------------------------------------------------
// FFMA micro-kernel (conv1)
template <int LDA>
__device__ __forceinline__ void mm32(const float* __restrict__ sA,
                                     const float* __restrict__ sB,
                                     int trow, int tcol, float acc[8][4]) {
#pragma unroll
    for (int k = 0; k < 32; ++k) {
        float4 b = *(const float4*)(sB + k * 64 + tcol);
#pragma unroll
        for (int i = 0; i < 8; ++i) {
            float a = sA[(trow + i) * LDA + k];
            acc[i][0] = fmaf(a, b.x, acc[i][0]);
            acc[i][1] = fmaf(a, b.y, acc[i][1]);
            acc[i][2] = fmaf(a, b.z, acc[i][2]);
            acc[i][3] = fmaf(a, b.w, acc[i][3]);
        }
    }
}

// conv1: h1 = relu((feats @ w1) * s1 + b1) -> bf16 hi/lo planes  (R5 version)
__global__ void __launch_bounds__(256) conv1_kernel(
    const float* __restrict__ feats, const float* __restrict__ w1,
    const float* __restrict__ s1, const float* __restrict__ b1, int n)
{
    __shared__ __align__(16) float sA[128 * 33];
    __shared__ __align__(16) float sB[32 * 64];
    const int tid = threadIdx.x;
    const int site0 = blockIdx.x * 128;
    const int trow = (tid >> 4) << 3;
    const int tcol = (tid & 15) << 2;

    float acc[8][4];
#pragma unroll
    for (int i = 0; i < 8; ++i)
#pragma unroll
        for (int j = 0; j < 4; ++j) acc[i][j] = 0.f;

#pragma unroll 1
    for (int k0 = 0; k0 < 256; k0 += 32) {
#pragma unroll
        for (int l = 0; l < 4; ++l) {
            int i = tid + l * 256;
            int r = i >> 3, c4 = (i & 7) << 2;
            int site = site0 + r;
            float4 v = make_float4(0.f, 0.f, 0.f, 0.f);
            if (site < n) v = *(const float4*)&feats[(size_t)site * 256 + k0 + c4];
            sA[r * 33 + c4 + 0] = v.x; sA[r * 33 + c4 + 1] = v.y;
            sA[r * 33 + c4 + 2] = v.z; sA[r * 33 + c4 + 3] = v.w;
        }
#pragma unroll
        for (int l = 0; l < 2; ++l) {
            int i = tid + l * 256;
            int r = i >> 4, c4 = (i & 15) << 2;
            *(float4*)&sB[r * 64 + c4] = *(const float4*)&w1[(size_t)(k0 + r) * 64 + c4];
        }
        __syncthreads();
        mm32<33>(sA, sB, trow, tcol, acc);
        __syncthreads();
    }

    float sc[4], bi[4];
#pragma unroll
    for (int j = 0; j < 4; ++j) { sc[j] = s1[tcol + j]; bi[j] = b1[tcol + j]; }
#pragma unroll
    for (int i = 0; i < 8; ++i) {
        int site = site0 + trow + i;   // < NMAX always; OOB rows never read back
        float v0 = fmaxf(fmaf(acc[i][0], sc[0], bi[0]), 0.f);
        float v1 = fmaxf(fmaf(acc[i][1], sc[1], bi[1]), 0.f);
        float v2 = fmaxf(fmaf(acc[i][2], sc[2], bi[2]), 0.f);
        float v3 = fmaxf(fmaf(acc[i][3], sc[3], bi[3]), 0.f);
        uint32_t h0, l0, h1v, l1v;
        bsplit2(v0, v1, h0, l0);
        bsplit2(v2, v3, h1v, l1v);
        unsigned char* row = g_h1b + (size_t)site * 256;
        *(uint2*)(row + tcol * 2)       = make_uint2(h0, h1v);   // hi plane
        *(uint2*)(row + 128 + tcol * 2) = make_uint2(l0, l1v);   // lo plane
    }
}

// ---------------------------------------------------------------------------
// FUSED conv2 + conv3 (block-phased, R5 gather, B fragments staged in smem):
//   h2 = relu(sparse3x3(h1) * s2 + b2)   (registers only, never stored)
//   out = relu((h2 @ w3) * s3 + b3 + feats)
#define LDP 144                        // bytes per row per plane
#define PLANE (128 * LDP)              // 18432
// dynamic smem layout (bytes):
#define SM_SC    0                     // 640 floats = 2560
#define SM_NBR   2560                  // 9*128*4 = 4608
#define SM_A     7680                  // 2 * PLANE = 36864 (hi, lo planes)
#define SM_B     (SM_A + 2 * PLANE)    // 44544: 1024 uint4 = 16384
#define SM_TOTAL (SM_B + 16384)        // 60928

__global__ void __launch_bounds__(256) conv23_kernel(
    const int* __restrict__ coords,
    const float* __restrict__ s2, const float* __restrict__ b2,
    const float* __restrict__ feats,
    const float* __restrict__ s3, const float* __restrict__ b3,
    float* __restrict__ out, int n)
{
    extern __shared__ __align__(128) char dsm[];
    float* s_s2 = (float*)(dsm + SM_SC);
    float* s_b2 = s_s2 + 64;
    float* s_s3 = s_b2 + 64;
    float* s_b3 = s_s3 + 256;
    int*  s_nbr = (int*)(dsm + SM_NBR);
    unsigned char* Abuf = (unsigned char*)(dsm + SM_A);
    uint4* Bsm = (uint4*)(dsm + SM_B);

    const int tid = threadIdx.x, wid = tid >> 5, lane = tid & 31;
    const int site0 = blockIdx.x * 128;
    const int rw = wid * 16;
    const int r2 = tid >> 1, half = tid & 1;   // gather: row, plane

    if (tid < 64) { s_s2[tid] = s2[tid]; s_b2[tid] = b2[tid]; }
    s_s3[tid] = s3[tid]; s_b3[tid] = b3[tid];
    if (tid < 128) {
#pragma unroll
        for (int t = 0; t < 9; ++t) s_nbr[t * 128 + tid] = -1;
        int site = site0 + tid;
        if (site < n) {
            int is64 = coords_is64(coords);
            int c = load_coord(coords, is64, site);
            int y = c / WGRID, x = c % WGRID;
#pragma unroll
            for (int t = 0; t < 9; ++t) {
                int ny = y + t / 3 - 1, nx = x + t % 3 - 1;
                if (ny >= 0 && ny < HGRID && nx >= 0 && nx < WGRID)
                    s_nbr[t * 128 + tid] = g_idx_map[ny * WGRID + nx];
            }
        }
    }
    __syncthreads();

    float acc[8][4];
#pragma unroll
    for (int t = 0; t < 8; ++t)
#pragma unroll
        for (int j = 0; j < 4; ++j) acc[t][j] = 0.f;

    uint4* mydst = (uint4*)(Abuf + half * PLANE + r2 * LDP);

    // ---------------- conv2: 9-tap sparse 3x3 accumulation ----------------
#pragma unroll 1
    for (int tap = 0; tap < 9; ++tap) {
        {   // gather A: copy 128B hi (half=0) or lo (half=1) per row (L2 hits)
            int nb = s_nbr[tap * 128 + r2];
            const uint4* src =
                (const uint4*)(g_h1b + (size_t)(nb < 0 ? 0 : nb) * 256 + half * 128);
            uint4 z = make_uint4(0, 0, 0, 0);
#pragma unroll
            for (int g = 0; g < 8; ++g) mydst[g] = (nb >= 0) ? src[g] : z;
        }
        {   // stage this tap's B fragments into smem (16KB, 64B/thread)
            const uint4* bs = g_w2f + (size_t)tap * 1024 + tid * 4;
#pragma unroll
            for (int q = 0; q < 4; ++q) Bsm[tid * 4 + q] = bs[q];
        }
        __syncthreads();

        // MMA: A from smem planes, B from smem fragments (LDS only)
#pragma unroll
        for (int kc = 0; kc < 4; ++kc) {
            uint32_t ab = (uint32_t)((rw + (lane >> 2)) * LDP + kc * 32 + (lane & 3) * 4);
            uint32_t ah[4], al[4];
            ah[0] = *(const uint32_t*)(Abuf + ab);
            ah[1] = *(const uint32_t*)(Abuf + ab + 8 * LDP);
            ah[2] = *(const uint32_t*)(Abuf + ab + 16);
            ah[3] = *(const uint32_t*)(Abuf + ab + 8 * LDP + 16);
            al[0] = *(const uint32_t*)(Abuf + PLANE + ab);
            al[1] = *(const uint32_t*)(Abuf + PLANE + ab + 8 * LDP);
            al[2] = *(const uint32_t*)(Abuf + PLANE + ab + 16);
            al[3] = *(const uint32_t*)(Abuf + PLANE + ab + 8 * LDP + 16);
#pragma unroll
            for (int nt = 0; nt < 8; ++nt) {
                uint4 b = Bsm[kc * 256 + nt * 32 + lane];
                mma16816(acc[nt], ah, b.x, b.y);
                mma16816(acc[nt], ah, b.z, b.w);
                mma16816(acc[nt], al, b.x, b.y);
            }
        }
        __syncthreads();   // A/B consumers done before next tap's writes
    }

    // ------- bn2 + relu in registers; repackage C-frags as A-frags --------
    uint32_t fh[4][4], fl[4][4];
    {
        const int n0 = (lane & 3) * 2;
#pragma unroll
        for (int kc = 0; kc < 4; ++kc) {
#pragma unroll
            for (int q = 0; q < 2; ++q) {
                int nt = 2 * kc + q;
                int c0 = nt * 8 + n0;
                float v0 = fmaxf(fmaf(acc[nt][0], s_s2[c0],     s_b2[c0]),     0.f);
                float v1 = fmaxf(fmaf(acc[nt][1], s_s2[c0 + 1], s_b2[c0 + 1]), 0.f);
                float v2 = fmaxf(fmaf(acc[nt][2], s_s2[c0],     s_b2[c0]),     0.f);
                float v3 = fmaxf(fmaf(acc[nt][3], s_s2[c0 + 1], s_b2[c0 + 1]), 0.f);
                bsplit2(v0, v1, fh[kc][2 * q],     fl[kc][2 * q]);
                bsplit2(v2, v3, fh[kc][2 * q + 1], fl[kc][2 * q + 1]);
            }
        }
    }

    // ---------------- conv3: 4 column blocks of 64, from registers --------
    float* stg = (float*)Abuf;   // 128 x 64 f32 staging = 32KB (fits A buffer)
    {   // preload cb=0 B fragments
        const uint4* bs = g_w3f + tid * 4;
#pragma unroll
        for (int q = 0; q < 4; ++q) Bsm[tid * 4 + q] = bs[q];
    }
    __syncthreads();

#pragma unroll 1
    for (int cb = 0; cb < 4; ++cb) {
        float acc2[8][4];
#pragma unroll
        for (int t = 0; t < 8; ++t)
#pragma unroll
            for (int j = 0; j < 4; ++j) acc2[t][j] = 0.f;

#pragma unroll
        for (int kc = 0; kc < 4; ++kc) {
#pragma unroll
            for (int nt = 0; nt < 8; ++nt) {
                uint4 b = Bsm[kc * 256 + nt * 32 + lane];
                mma16816(acc2[nt], fh[kc], b.x, b.y);
                mma16816(acc2[nt], fh[kc], b.z, b.w);
                mma16816(acc2[nt], fl[kc], b.x, b.y);
            }
        }
        __syncthreads();   // B reads done; stg free (prev write-out done)
        {
            int r0 = rw + (lane >> 2);
            int n0 = (lane & 3) * 2;
#pragma unroll
            for (int nt = 0; nt < 8; ++nt) {
                int c  = nt * 8 + n0;
                int cg = cb * 64 + c;
                stg[r0 * 64 + c]           = fmaf(acc2[nt][0], s_s3[cg],     s_b3[cg]);
                stg[r0 * 64 + c + 1]       = fmaf(acc2[nt][1], s_s3[cg + 1], s_b3[cg + 1]);
                stg[(r0 + 8) * 64 + c]     = fmaf(acc2[nt][2], s_s3[cg],     s_b3[cg]);
                stg[(r0 + 8) * 64 + c + 1] = fmaf(acc2[nt][3], s_s3[cg + 1], s_b3[cg + 1]);
            }
        }
        if (cb < 3) {   // stage next cb's B fragments
            const uint4* bs = g_w3f + (size_t)(cb + 1) * 1024 + tid * 4;
#pragma unroll
            for (int q = 0; q < 4; ++q) Bsm[tid * 4 + q] = bs[q];
        }
        __syncthreads();   // stg + next B visible
        {
            int site = site0 + r2;
            if (site < n) {
                const float4* idn =
                    (const float4*)&feats[(size_t)site * 256 + cb * 64 + half * 32];
                const float4* s = (const float4*)(stg + r2 * 64 + half * 32);
                float4* dst = (float4*)&out[(size_t)site * 256 + cb * 64 + half * 32];
#pragma unroll
                for (int j = 0; j < 8; ++j) {
                    float4 a = s[j], b = idn[j], o;
                    o.x = fmaxf(a.x + b.x, 0.f);
                    o.y = fmaxf(a.y + b.y, 0.f);
                    o.z = fmaxf(a.z + b.z, 0.f);
                    o.w = fmaxf(a.w + b.w, 0.f);
                    dst[j] = o;
                }
            }
        }
    }
}

// ---------------------------------------------------------------------------
extern "C" void kernel_launch(void* const* d_in, const int* in_sizes, int n_in,
                              void* d_out, int out_size) {
    const float* feats  = (const float*)d_in[0];
    const int*   coords = (const int*)d_in[1];
    const float* w1     = (const float*)d_in[2];
    const float* w2     = (const float*)d_in[3];
    const float* w3     = (const float*)d_in[4];
    const float* s1     = (const float*)d_in[5];
    const float* b1     = (const float*)d_in[6];
    const float* s2     = (const float*)d_in[7];
    const float* b2     = (const float*)d_in[8];
    const float* s3     = (const float*)d_in[9];
    const float* b3     = (const float*)d_in[10];
    float* out = (float*)d_out;

    const int n = in_sizes[0] / 256;
    const int tiles = (n + 127) / 128;

    cudaFuncSetAttribute(conv23_kernel,
                         cudaFuncAttributeMaxDynamicSharedMemorySize, SM_TOTAL);

    // 4 launches; conv23 is launch #4 so ncu (-s/-c window) captures it.
    util1_kernel<<<(HGRID * WGRID + 255) / 256, 256>>>(w2);                 // #1
    util2_kernel<<<(max(n, 4096) + 255) / 256, 256>>>(coords, w3, n);       // #2
    conv1_kernel<<<tiles, 256>>>(feats, w1, s1, b1, n);                     // #3
    conv23_kernel<<<tiles, 256, SM_TOTAL>>>(coords, s2, b2, feats, s3, b3, out, n);  // #4
}